// round 13
// baseline (speedup 1.0000x reference)
#include <cuda_runtime.h>
#include <cuda_fp16.h>
#include <cstdint>

#define NH       128
#define ET       128          // edges per tile
#define THREADS  256          // 8 warps, 32x64 warp tiles

// ---------------- smem layout (bytes) ----------------
#define OFF_RIDX 0                   // int[2][128]
#define OFF_CIDX 1024                // int[2][128]
#define OFF_A0   2048                // 128 rows x 256B (fp16)
#define OFF_A1   (OFF_A0 + 32768)
#define OFF_BW   (OFF_A1 + 32768)    // 4 resident weight images
#define SMEM_TOTAL (OFF_BW + 4*32768)   // 198656 B -> 1 CTA/SM, persistent

#define MAX_NODES 131072

// ---------------- device scratch (no allocs allowed) ----------------
__device__ uint4 g_xh[MAX_NODES * 16];    // [node][128] fp16 (16B chunks, linear)
__device__ uint4 g_wimg[4][2048];         // B'[n][k] fp16, swizzled 32KB images

// ---------------- helpers ----------------
__device__ __forceinline__ uint32_t smem_u32(const void* p) {
    uint32_t a;
    asm("{ .reg .u64 t; cvta.to.shared.u64 t, %1; cvt.u32.u64 %0, t; }" : "=r"(a) : "l"(p));
    return a;
}
__device__ __forceinline__ float frelu(float v) { return fmaxf(v, 0.0f); }

__device__ __forceinline__ uint32_t packh2(float a, float b) {
    __half2 h = __floats2half2_rn(a, b);
    return *reinterpret_cast<uint32_t*>(&h);
}

__device__ __forceinline__ void cp16(uint32_t smem_dst, const void* gsrc) {
    asm volatile("cp.async.cg.shared.global [%0], [%1], 16;"
                 :: "r"(smem_dst), "l"(gsrc) : "memory");
}
__device__ __forceinline__ void cp_commit() {
    asm volatile("cp.async.commit_group;" ::: "memory");
}
__device__ __forceinline__ void cp_wait0() {
    asm volatile("cp.async.wait_group 0;" ::: "memory");
}

__device__ __forceinline__ void ldsm_x4(uint32_t (&r)[4], uint32_t addr) {
    asm volatile("ldmatrix.sync.aligned.m8n8.x4.shared.b16 {%0,%1,%2,%3}, [%4];"
        : "=r"(r[0]), "=r"(r[1]), "=r"(r[2]), "=r"(r[3]) : "r"(addr));
}
__device__ __forceinline__ void ldsm_x2(uint32_t (&r)[2], uint32_t addr) {
    asm volatile("ldmatrix.sync.aligned.m8n8.x2.shared.b16 {%0,%1}, [%2];"
        : "=r"(r[0]), "=r"(r[1]) : "r"(addr));
}
__device__ __forceinline__ void mma16816(float (&d)[4], const uint32_t (&a)[4],
                                         const uint32_t (&b)[2]) {
    asm volatile("mma.sync.aligned.m16n8k16.row.col.f32.f16.f16.f32 "
        "{%0,%1,%2,%3}, {%4,%5,%6,%7}, {%8,%9}, {%0,%1,%2,%3};"
        : "+f"(d[0]), "+f"(d[1]), "+f"(d[2]), "+f"(d[3])
        : "r"(a[0]), "r"(a[1]), "r"(a[2]), "r"(a[3]), "r"(b[0]), "r"(b[1]));
}

// ================= prep kernels =================
// B'[n][k] = W[k][n], row n = 256B, 16B chunk c placed at (c ^ (n&7))
__global__ void prep_w_kernel(const float* __restrict__ Wm, const float* __restrict__ We) {
    int idx = blockIdx.x * blockDim.x + threadIdx.x;   // < 4*16384
    if (idx >= 65536) return;
    int mat = idx >> 14, e = idx & 16383;
    int n = e >> 7, k = e & 127;
    float v = (mat < 3) ? Wm[(mat * 128 + k) * 128 + n] : We[k * 128 + n];
    uint32_t pos = (uint32_t)(n * 256 + (((k >> 3) ^ (n & 7)) << 4) + ((k & 7) << 1));
    *(__half*)((char*)g_wimg[mat] + pos) = __float2half_rn(v);
}

__global__ void prep_x_kernel(const float* __restrict__ x, long long total) {
    long long idx = (long long)blockIdx.x * blockDim.x + threadIdx.x;
    if (idx >= total) return;
    ((__half*)g_xh)[idx] = __float2half_rn(x[idx]);
}

// ===== warp GEMM: acc += A(128x128 fp16) @ B^T, warp tile 32x64, 1-term =====
__device__ __forceinline__ void do_gemm(uint32_t sb, uint32_t aOff, uint32_t bOff,
                                        float (&acc)[2][8][4],
                                        int wm, int wn, int lane) {
    const int sx = lane & 7;
    const int aR = 32 * wm + sx + ((lane >> 3) & 1) * 8;
    const int aK = (lane >> 4) & 1;
    const int bR = 64 * wn + sx;
    const int bK = (lane >> 3) & 1;
    const uint32_t aBase = sb + aOff + (uint32_t)aR * 256;
    const uint32_t bBase = sb + bOff + (uint32_t)bR * 256;

    #pragma unroll 1
    for (int ks = 0; ks < 8; ks++) {
        uint32_t ah[2][4];
        #pragma unroll
        for (int mt = 0; mt < 2; mt++) {
            uint32_t off = (uint32_t)(mt * 16 * 256) + ((uint32_t)((2 * ks + aK) ^ sx) << 4);
            ldsm_x4(ah[mt], aBase + off);
        }
        #pragma unroll
        for (int nt = 0; nt < 8; nt++) {
            uint32_t off = (uint32_t)(nt * 8 * 256) + ((uint32_t)((2 * ks + bK) ^ sx) << 4);
            uint32_t bh[2];
            ldsm_x2(bh, bBase + off);
            #pragma unroll
            for (int mt = 0; mt < 2; mt++) {
                mma16816(acc[mt][nt], ah[mt], bh);
            }
        }
    }
}

// ================= persistent fused kernel =================
__global__ void __launch_bounds__(THREADS, 1)
edge_conv_mma(const float* __restrict__ eattr,
              const int*   __restrict__ eidx,
              const float* __restrict__ bm,
              const float* __restrict__ be,
              float* __restrict__ out,
              int E, int n_nodes)
{
    extern __shared__ char smc[];
    const uint32_t sb = smem_u32(smc);
    int* ridx = (int*)(smc + OFF_RIDX);   // [2][128]
    int* cidx = (int*)(smc + OFF_CIDX);   // [2][128]

    const int tid  = threadIdx.x;
    const int wid  = tid >> 5;
    const int lane = tid & 31;
    const int wm   = wid & 3;          // row group (32 edges)
    const int wn   = wid >> 2;         // col group (64 cols)
    const int ntiles = (E + ET - 1) / ET;

    // ---- prologue: resident weights (4 x 32KB) ----
    #pragma unroll
    for (int it = 0; it < 32; it++) {
        int i = tid + it * THREADS;              // < 8192
        cp16(sb + OFF_BW + i * 16, (const uint4*)g_wimg + i);
    }
    // idx for first tile (parity 0)
    if (tid < ET) {
        long long e = (long long)blockIdx.x * ET + tid; if (e >= E) e = E - 1;
        int r = eidx[e];
        int c = eidx[(long long)E + e];
        ridx[tid] = min(max(r, 0), n_nodes - 1);
        cidx[tid] = min(max(c, 0), n_nodes - 1);
    }
    cp_commit();
    __syncthreads();   // idx visible

    // prefetch seg0(tile0) -> A0
    #pragma unroll
    for (int it = 0; it < 8; it++) {
        int i = tid + it * THREADS;
        int e = i >> 4, c = i & 15;
        int node = ridx[e];
        uint32_t off = (uint32_t)(e * 256 + ((c ^ (e & 7)) << 4));
        cp16(sb + OFF_A0 + off, &g_xh[node * 16 + c]);
    }
    cp_commit();

    uint32_t offX = OFF_A0, offY = OFF_A1;
    int par = 0;

    for (int tile = blockIdx.x; tile < ntiles; tile += gridDim.x) {
        cp_wait0();        // seg0 in X (+ weights on first iter)
        __syncthreads();

        const long long e0 = (long long)tile * ET;

        float acc[2][8][4];
        #pragma unroll
        for (int i = 0; i < 2; i++)
            #pragma unroll
            for (int j = 0; j < 8; j++)
                #pragma unroll
                for (int q = 0; q < 4; q++) acc[i][j][q] = 0.0f;

        // --- issue seg1 -> Y (group G1) ---
        {
            const int* ci = cidx + par * ET;
            #pragma unroll
            for (int it = 0; it < 8; it++) {
                int i = tid + it * THREADS;
                int e = i >> 4, c = i & 15;
                int node = ci[e];
                uint32_t off = (uint32_t)(e * 256 + ((c ^ (e & 7)) << 4));
                cp16(sb + offY + off, &g_xh[node * 16 + c]);
            }
            cp_commit();
        }
        // --- write next tile's idx into the other parity slot ---
        if (tid < ET) {
            long long ne = (long long)(tile + gridDim.x) * ET + tid;
            if (ne >= E) ne = E - 1;
            int r = eidx[ne];
            int c = eidx[(long long)E + ne];
            ridx[(par ^ 1) * ET + tid] = min(max(r, 0), n_nodes - 1);
            cidx[(par ^ 1) * ET + tid] = min(max(c, 0), n_nodes - 1);
        }

        // =========== GEMM seg0 (X) ===========
        do_gemm(sb, offX, OFF_BW + 0 * 32768, acc, wm, wn, lane);

        cp_wait0();        // seg1 landed in Y
        __syncthreads();   // + gemm(seg0) done by all -> X writable later, next-idx visible

        // =========== GEMM seg1 (Y) ===========
        do_gemm(sb, offY, OFF_BW + 1 * 32768, acc, wm, wn, lane);
        __syncthreads();   // all done reading Y

        // --- issue seg0(next tile) -> Y (group G2) ---
        {
            const int* ri = ridx + (par ^ 1) * ET;
            #pragma unroll
            for (int it = 0; it < 8; it++) {
                int i = tid + it * THREADS;
                int e = i >> 4, c = i & 15;
                int node = ri[e];
                uint32_t off = (uint32_t)(e * 256 + ((c ^ (e & 7)) << 4));
                cp16(sb + offY + off, &g_xh[node * 16 + c]);
            }
            cp_commit();
        }

        // --- stage eattr (fp32 -> fp16) into X ---
        #pragma unroll 4
        for (int it = 0; it < 8; it++) {
            int i = tid + it * THREADS;
            int e = i >> 4, c = i & 15;
            long long ge = e0 + e; if (ge >= E) ge = E - 1;
            const float4* s = (const float4*)(eattr + ge * NH + c * 8);
            float4 fa = __ldg(s), fb = __ldg(s + 1);
            uint4 h;
            h.x = packh2(fa.x, fa.y);
            h.y = packh2(fa.z, fa.w);
            h.z = packh2(fb.x, fb.y);
            h.w = packh2(fb.z, fb.w);
            uint32_t off = (uint32_t)(e * 256 + ((c ^ (e & 7)) << 4));
            *(uint4*)(smc + offX + off) = h;
        }
        __syncthreads();

        // =========== GEMM seg2 (X = eattr) ===========
        do_gemm(sb, offX, OFF_BW + 2 * 32768, acc, wm, wn, lane);
        __syncthreads();

        // ==== epilogue 1: ea2 = eattr + relu(msg + bm), RMW X in place ====
        {
            const int rq = lane >> 2;
            const int cq = (lane & 3) * 2;
            #pragma unroll
            for (int mt = 0; mt < 2; mt++) {
                int row0 = 32 * wm + 16 * mt + rq;
                #pragma unroll
                for (int nt = 0; nt < 8; nt++) {
                    int c = 64 * wn + 8 * nt + cq;
                    float2 bmv = __ldg((const float2*)(bm + c));
                    #pragma unroll
                    for (int h = 0; h < 2; h++) {
                        int row = row0 + 8 * h;
                        uint32_t addr = (uint32_t)(row * 256 +
                                        (((c >> 3) ^ (row & 7)) << 4) + ((c & 7) << 1));
                        uint32_t hu = *(uint32_t*)(smc + offX + addr);
                        __half2 hb = *(__half2*)&hu;
                        float ev0 = __half2float(__low2half(hb));
                        float ev1 = __half2float(__high2half(hb));
                        float v0 = ev0 + frelu(acc[mt][nt][2 * h + 0] + bmv.x);
                        float v1 = ev1 + frelu(acc[mt][nt][2 * h + 1] + bmv.y);
                        *(uint32_t*)(smc + offX + addr) = packh2(v0, v1);
                        acc[mt][nt][2 * h + 0] = 0.0f;
                        acc[mt][nt][2 * h + 1] = 0.0f;
                    }
                }
            }
        }
        __syncthreads();   // ea2 complete across warps

        // =========== GEMM 2 (X = ea2, W_edge resident) ===========
        do_gemm(sb, offX, OFF_BW + 3 * 32768, acc, wm, wn, lane);

        // =========== epilogue 2: out = relu(acc + be) ===========
        {
            const int rq = lane >> 2;
            const int cq = (lane & 3) * 2;
            #pragma unroll
            for (int mt = 0; mt < 2; mt++) {
                int row0 = 32 * wm + 16 * mt + rq;
                #pragma unroll
                for (int nt = 0; nt < 8; nt++) {
                    int c = 64 * wn + 8 * nt + cq;
                    float2 bev = __ldg((const float2*)(be + c));
                    #pragma unroll
                    for (int h = 0; h < 2; h++) {
                        int row = row0 + 8 * h;
                        long long ge = e0 + row;
                        if (ge < E) {
                            float2 o;
                            o.x = frelu(acc[mt][nt][2 * h + 0] + bev.x);
                            o.y = frelu(acc[mt][nt][2 * h + 1] + bev.y);
                            *(float2*)(out + ge * NH + c) = o;
                        }
                    }
                }
            }
        }

        // swap buffers / parity
        uint32_t t = offX; offX = offY; offY = t;
        par ^= 1;
    }
}

// ================= host =================
extern "C" void kernel_launch(void* const* d_in, const int* in_sizes, int n_in,
                              void* d_out, int out_size)
{
    const float* x     = (const float*)d_in[0];
    const float* eattr = (const float*)d_in[1];
    const int*   eidx  = (const int*)d_in[2];   // int32 (JAX canonicalizes int64->int32)
    const float* Wm    = (const float*)d_in[3];
    const float* bm    = (const float*)d_in[4];
    const float* We    = (const float*)d_in[5];
    const float* be    = (const float*)d_in[6];
    float*       out   = (float*)d_out;

    const int E  = in_sizes[2] / 2;
    int n_nodes  = in_sizes[0] / NH;
    if (n_nodes > MAX_NODES) n_nodes = MAX_NODES;

    prep_w_kernel<<<(65536 + 255) / 256, 256>>>(Wm, We);
    long long xt = (long long)n_nodes * NH;
    prep_x_kernel<<<(unsigned)((xt + 255) / 256), 256>>>(x, xt);

    cudaFuncSetAttribute(edge_conv_mma,
                         cudaFuncAttributeMaxDynamicSharedMemorySize, SMEM_TOTAL);

    int nsm = 148;
    cudaDeviceGetAttribute(&nsm, cudaDevAttrMultiProcessorCount, 0);
    const int ntiles = (E + ET - 1) / ET;
    int grid = nsm < ntiles ? nsm : ntiles;

    edge_conv_mma<<<grid, THREADS, SMEM_TOTAL>>>(eattr, eidx, bm, be, out, E, n_nodes);
}

// round 14
// speedup vs baseline: 1.2823x; 1.2823x over previous
#include <cuda_runtime.h>
#include <cuda_fp16.h>
#include <cstdint>

#define NH       128
#define ET       128          // edges (or nodes) per tile
#define THREADS  256          // 8 warps, 32x64 warp tiles

// ---------------- smem layout (bytes): A + two resident B images ----------------
#define OFF_A    0             // 128 rows x 256B (fp16)
#define OFF_WA   32768
#define OFF_WB   65536
#define SMEM_TOTAL 98304       // 96KB -> 2 CTAs/SM

#define MAX_NODES 131072

// ---------------- device scratch (no allocs allowed) ----------------
__device__ uint4    g_wimg[4][2048];        // B'[n][k] fp16, swizzled 32KB images
__device__ uint32_t g_U[MAX_NODES * 64];    // u' = x@W0 + bm, fp16x2 [node][64]
__device__ uint32_t g_V[MAX_NODES * 64];    // v  = x@W1,      fp16x2 [node][64]

// ---------------- helpers ----------------
__device__ __forceinline__ uint32_t smem_u32(const void* p) {
    uint32_t a;
    asm("{ .reg .u64 t; cvta.to.shared.u64 t, %1; cvt.u32.u64 %0, t; }" : "=r"(a) : "l"(p));
    return a;
}
__device__ __forceinline__ float frelu(float v) { return fmaxf(v, 0.0f); }

__device__ __forceinline__ uint32_t packh2(float a, float b) {
    __half2 h = __floats2half2_rn(a, b);
    return *reinterpret_cast<uint32_t*>(&h);
}
__device__ __forceinline__ float2 unpackh2(uint32_t u) {
    __half2 h = *reinterpret_cast<__half2*>(&u);
    return make_float2(__half2float(__low2half(h)), __half2float(__high2half(h)));
}

__device__ __forceinline__ void cp16(uint32_t smem_dst, const void* gsrc) {
    asm volatile("cp.async.cg.shared.global [%0], [%1], 16;"
                 :: "r"(smem_dst), "l"(gsrc) : "memory");
}
__device__ __forceinline__ void cp_commit() {
    asm volatile("cp.async.commit_group;" ::: "memory");
}
__device__ __forceinline__ void cp_wait0() {
    asm volatile("cp.async.wait_group 0;" ::: "memory");
}

__device__ __forceinline__ void ldsm_x4(uint32_t (&r)[4], uint32_t addr) {
    asm volatile("ldmatrix.sync.aligned.m8n8.x4.shared.b16 {%0,%1,%2,%3}, [%4];"
        : "=r"(r[0]), "=r"(r[1]), "=r"(r[2]), "=r"(r[3]) : "r"(addr));
}
__device__ __forceinline__ void ldsm_x2(uint32_t (&r)[2], uint32_t addr) {
    asm volatile("ldmatrix.sync.aligned.m8n8.x2.shared.b16 {%0,%1}, [%2];"
        : "=r"(r[0]), "=r"(r[1]) : "r"(addr));
}
__device__ __forceinline__ void mma16816(float (&d)[4], const uint32_t (&a)[4],
                                         const uint32_t (&b)[2]) {
    asm volatile("mma.sync.aligned.m16n8k16.row.col.f32.f16.f16.f32 "
        "{%0,%1,%2,%3}, {%4,%5,%6,%7}, {%8,%9}, {%0,%1,%2,%3};"
        : "+f"(d[0]), "+f"(d[1]), "+f"(d[2]), "+f"(d[3])
        : "r"(a[0]), "r"(a[1]), "r"(a[2]), "r"(a[3]), "r"(b[0]), "r"(b[1]));
}

// ===== warp GEMM: acc += A(128x128 fp16) @ B^T, warp tile 32x64 =====
__device__ __forceinline__ void do_gemm(uint32_t sb, uint32_t aOff, uint32_t bOff,
                                        float (&acc)[2][8][4],
                                        int wm, int wn, int lane) {
    const int sx = lane & 7;
    const int aR = 32 * wm + sx + ((lane >> 3) & 1) * 8;
    const int aK = (lane >> 4) & 1;
    const int bR = 64 * wn + sx;
    const int bK = (lane >> 3) & 1;
    const uint32_t aBase = sb + aOff + (uint32_t)aR * 256;
    const uint32_t bBase = sb + bOff + (uint32_t)bR * 256;

    #pragma unroll 1
    for (int ks = 0; ks < 8; ks++) {
        uint32_t ah[2][4];
        #pragma unroll
        for (int mt = 0; mt < 2; mt++) {
            uint32_t off = (uint32_t)(mt * 16 * 256) + ((uint32_t)((2 * ks + aK) ^ sx) << 4);
            ldsm_x4(ah[mt], aBase + off);
        }
        #pragma unroll
        for (int nt = 0; nt < 8; nt++) {
            uint32_t off = (uint32_t)(nt * 8 * 256) + ((uint32_t)((2 * ks + bK) ^ sx) << 4);
            uint32_t bh[2];
            ldsm_x2(bh, bBase + off);
            #pragma unroll
            for (int mt = 0; mt < 2; mt++) {
                mma16816(acc[mt][nt], ah[mt], bh);
            }
        }
    }
}

// ================= prep kernel 1: weight images =================
// B'[n][k] = W[k][n], row n = 256B, 16B chunk c placed at (c ^ (n&7))
__global__ void prep_w_kernel(const float* __restrict__ Wm, const float* __restrict__ We) {
    int idx = blockIdx.x * blockDim.x + threadIdx.x;   // < 4*16384
    if (idx >= 65536) return;
    int mat = idx >> 14, e = idx & 16383;
    int n = e >> 7, k = e & 127;
    float v = (mat < 3) ? Wm[(mat * 128 + k) * 128 + n] : We[k * 128 + n];
    uint32_t pos = (uint32_t)(n * 256 + (((k >> 3) ^ (n & 7)) << 4) + ((k & 7) << 1));
    *(__half*)((char*)g_wimg[mat] + pos) = __float2half_rn(v);
}

// ================= prep kernel 2: U = x@W0 + bm, V = x@W1 (per node) =========
__global__ void __launch_bounds__(THREADS, 2)
prep_uv_kernel(const float* __restrict__ x, const float* __restrict__ bm, int n_nodes)
{
    extern __shared__ char smc[];
    const uint32_t sb = smem_u32(smc);
    const int tid  = threadIdx.x;
    const int wid  = tid >> 5;
    const int lane = tid & 31;
    const int wm   = wid & 3;
    const int wn   = wid >> 2;
    const int t0   = blockIdx.x * ET;

    // stage W0,W1 images (contiguous in g_wimg)
    #pragma unroll
    for (int it = 0; it < 16; it++) {
        int i = tid + it * THREADS;              // < 4096
        cp16(sb + OFF_WA + i * 16, (const uint4*)g_wimg + i);
    }
    cp_commit();

    // stage x tile fp32 -> fp16 into A
    #pragma unroll 4
    for (int it = 0; it < 8; it++) {
        int i = tid + it * THREADS;
        int e = i >> 4, c = i & 15;
        int node = t0 + e; if (node >= n_nodes) node = n_nodes - 1;
        const float4* s = (const float4*)(x + (long long)node * NH + c * 8);
        float4 fa = __ldg(s), fb = __ldg(s + 1);
        uint4 h;
        h.x = packh2(fa.x, fa.y);
        h.y = packh2(fa.z, fa.w);
        h.z = packh2(fb.x, fb.y);
        h.w = packh2(fb.z, fb.w);
        uint32_t off = (uint32_t)(e * 256 + ((c ^ (e & 7)) << 4));
        *(uint4*)(smc + OFF_A + off) = h;
    }
    cp_wait0();
    __syncthreads();

    float acc[2][8][4];
    #pragma unroll
    for (int i = 0; i < 2; i++)
        #pragma unroll
        for (int j = 0; j < 8; j++)
            #pragma unroll
            for (int q = 0; q < 4; q++) acc[i][j][q] = 0.0f;

    // U = A @ W0^T + bm
    do_gemm(sb, OFF_A, OFF_WA, acc, wm, wn, lane);
    {
        const int rq = lane >> 2;
        const int cq = (lane & 3) * 2;
        #pragma unroll
        for (int mt = 0; mt < 2; mt++) {
            #pragma unroll
            for (int nt = 0; nt < 8; nt++) {
                int c = 64 * wn + 8 * nt + cq;
                float2 bmv = __ldg((const float2*)(bm + c));
                #pragma unroll
                for (int h = 0; h < 2; h++) {
                    int node = t0 + 32 * wm + 16 * mt + 8 * h + rq;
                    if (node < n_nodes)
                        g_U[node * 64 + (c >> 1)] =
                            packh2(acc[mt][nt][2*h+0] + bmv.x, acc[mt][nt][2*h+1] + bmv.y);
                    acc[mt][nt][2*h+0] = 0.0f;
                    acc[mt][nt][2*h+1] = 0.0f;
                }
            }
        }
    }

    // V = A @ W1^T
    do_gemm(sb, OFF_A, OFF_WB, acc, wm, wn, lane);
    {
        const int rq = lane >> 2;
        const int cq = (lane & 3) * 2;
        #pragma unroll
        for (int mt = 0; mt < 2; mt++) {
            #pragma unroll
            for (int nt = 0; nt < 8; nt++) {
                int c = 64 * wn + 8 * nt + cq;
                #pragma unroll
                for (int h = 0; h < 2; h++) {
                    int node = t0 + 32 * wm + 16 * mt + 8 * h + rq;
                    if (node < n_nodes)
                        g_V[node * 64 + (c >> 1)] =
                            packh2(acc[mt][nt][2*h+0], acc[mt][nt][2*h+1]);
                }
            }
        }
    }
}

// ================= main persistent kernel =================
__global__ void __launch_bounds__(THREADS, 2)
edge_conv_mma(const float* __restrict__ eattr,
              const int*   __restrict__ eidx,
              const float* __restrict__ be,
              float* __restrict__ out,
              int E, int n_nodes)
{
    extern __shared__ char smc[];
    const uint32_t sb = smem_u32(smc);

    const int tid  = threadIdx.x;
    const int wid  = tid >> 5;
    const int lane = tid & 31;
    const int wm   = wid & 3;          // row group (32 edges)
    const int wn   = wid >> 2;         // col group (64 cols)
    const int ntiles = (E + ET - 1) / ET;

    // ---- prologue: resident W2 (msg/eattr part) + W3 (W_edge) images ----
    #pragma unroll
    for (int it = 0; it < 16; it++) {
        int i = tid + it * THREADS;              // < 4096
        cp16(sb + OFF_WA + i * 16, (const uint4*)g_wimg + 2 * 2048 + i);
    }
    cp_commit();

    for (int tile = blockIdx.x; tile < ntiles; tile += gridDim.x) {
        const long long e0 = (long long)tile * ET;

        // --- stage eattr (fp32 -> fp16) into A ---
        #pragma unroll 4
        for (int it = 0; it < 8; it++) {
            int i = tid + it * THREADS;
            int e = i >> 4, c = i & 15;
            long long ge = e0 + e; if (ge >= E) ge = E - 1;
            const float4* s = (const float4*)(eattr + ge * NH + c * 8);
            float4 fa = __ldg(s), fb = __ldg(s + 1);
            uint4 h;
            h.x = packh2(fa.x, fa.y);
            h.y = packh2(fa.z, fa.w);
            h.z = packh2(fb.x, fb.y);
            h.w = packh2(fb.z, fb.w);
            uint32_t off = (uint32_t)(e * 256 + ((c ^ (e & 7)) << 4));
            *(uint4*)(smc + OFF_A + off) = h;
        }
        cp_wait0();        // weights resident (no-op after first tile)
        __syncthreads();

        float acc[2][8][4];
        #pragma unroll
        for (int i = 0; i < 2; i++)
            #pragma unroll
            for (int j = 0; j < 8; j++)
                #pragma unroll
                for (int q = 0; q < 4; q++) acc[i][j][q] = 0.0f;

        // =========== GEMM 1: ea @ W2 ===========
        do_gemm(sb, OFF_A, OFF_WA, acc, wm, wn, lane);
        __syncthreads();   // A readers done before epi1 RMW

        // ==== epilogue 1: ea2 = ea + relu(u[row] + v[col] + ea@W2), RMW A ====
        {
            const int rq = lane >> 2;          // 0..7
            const int cq = (lane & 3) * 2;     // 0,2,4,6
            #pragma unroll
            for (int mt = 0; mt < 2; mt++) {
                #pragma unroll
                for (int h = 0; h < 2; h++) {
                    int row = 32 * wm + 16 * mt + 8 * h + rq;
                    long long ge = e0 + row; if (ge >= E) ge = E - 1;
                    int rn = __ldg(eidx + ge);
                    int cn = __ldg(eidx + (long long)E + ge);
                    rn = min(max(rn, 0), n_nodes - 1);
                    cn = min(max(cn, 0), n_nodes - 1);
                    const uint32_t* urow = g_U + rn * 64;
                    const uint32_t* vrow = g_V + cn * 64;
                    #pragma unroll
                    for (int nt = 0; nt < 8; nt++) {
                        int c = 64 * wn + 8 * nt + cq;
                        float2 uv = unpackh2(__ldg(urow + (c >> 1)));
                        float2 vv = unpackh2(__ldg(vrow + (c >> 1)));
                        uint32_t addr = (uint32_t)(row * 256 +
                                        (((c >> 3) ^ (row & 7)) << 4) + ((c & 7) << 1));
                        float2 ea = unpackh2(*(uint32_t*)(smc + OFF_A + addr));
                        float v0 = ea.x + frelu(acc[mt][nt][2*h+0] + uv.x + vv.x);
                        float v1 = ea.y + frelu(acc[mt][nt][2*h+1] + uv.y + vv.y);
                        *(uint32_t*)(smc + OFF_A + addr) = packh2(v0, v1);
                        acc[mt][nt][2*h+0] = 0.0f;
                        acc[mt][nt][2*h+1] = 0.0f;
                    }
                }
            }
        }
        __syncthreads();   // ea2 complete across warps

        // =========== GEMM 2: ea2 @ W_edge ===========
        do_gemm(sb, OFF_A, OFF_WB, acc, wm, wn, lane);
        __syncthreads();   // A consumed -> next tile may restage

        // =========== epilogue 2: out = relu(acc + be) ===========
        {
            const int rq = lane >> 2;
            const int cq = (lane & 3) * 2;
            #pragma unroll
            for (int mt = 0; mt < 2; mt++) {
                #pragma unroll
                for (int nt = 0; nt < 8; nt++) {
                    int c = 64 * wn + 8 * nt + cq;
                    float2 bev = __ldg((const float2*)(be + c));
                    #pragma unroll
                    for (int h = 0; h < 2; h++) {
                        int row = 32 * wm + 16 * mt + 8 * h + rq;
                        long long ge = e0 + row;
                        if (ge < E) {
                            float2 o;
                            o.x = frelu(acc[mt][nt][2*h+0] + bev.x);
                            o.y = frelu(acc[mt][nt][2*h+1] + bev.y);
                            *(float2*)(out + ge * NH + c) = o;
                        }
                    }
                }
            }
        }
    }
}

// ================= host =================
extern "C" void kernel_launch(void* const* d_in, const int* in_sizes, int n_in,
                              void* d_out, int out_size)
{
    const float* x     = (const float*)d_in[0];
    const float* eattr = (const float*)d_in[1];
    const int*   eidx  = (const int*)d_in[2];   // int32 (JAX canonicalizes int64->int32)
    const float* Wm    = (const float*)d_in[3];
    const float* bm    = (const float*)d_in[4];
    const float* We    = (const float*)d_in[5];
    const float* be    = (const float*)d_in[6];
    float*       out   = (float*)d_out;

    const int E  = in_sizes[2] / 2;
    int n_nodes  = in_sizes[0] / NH;
    if (n_nodes > MAX_NODES) n_nodes = MAX_NODES;

    prep_w_kernel<<<(65536 + 255) / 256, 256>>>(Wm, We);

    cudaFuncSetAttribute(prep_uv_kernel,
                         cudaFuncAttributeMaxDynamicSharedMemorySize, SMEM_TOTAL);
    cudaFuncSetAttribute(edge_conv_mma,
                         cudaFuncAttributeMaxDynamicSharedMemorySize, SMEM_TOTAL);

    const int ntileN = (n_nodes + ET - 1) / ET;
    prep_uv_kernel<<<ntileN, THREADS, SMEM_TOTAL>>>(x, bm, n_nodes);

    int nsm = 148;
    cudaDeviceGetAttribute(&nsm, cudaDevAttrMultiProcessorCount, 0);
    const int ntiles = (E + ET - 1) / ET;
    int grid = 2 * nsm < ntiles ? 2 * nsm : ntiles;

    edge_conv_mma<<<grid, THREADS, SMEM_TOTAL>>>(eattr, eidx, be, out, E, n_nodes);
}

// round 15
// speedup vs baseline: 1.4752x; 1.1505x over previous
#include <cuda_runtime.h>
#include <cuda_fp16.h>
#include <cstdint>

#define NH       128
#define ET       128          // edges (or nodes) per tile
#define THREADS  256          // 8 warps, 32x64 warp tiles

// ---------------- smem layout (bytes): A + two resident B images ----------------
#define OFF_A    0             // 128 rows x 256B (fp16)
#define OFF_WA   32768
#define OFF_WB   65536
#define SMEM_TOTAL 98304       // 96KB -> 2 CTAs/SM

#define MAX_NODES 131072

// ---------------- device scratch (no allocs allowed) ----------------
__device__ uint4    g_wimg[4][2048];        // B'[n][k] fp16, swizzled+permuted 32KB images
__device__ uint32_t g_U[MAX_NODES * 64];    // u' = x@W0 + bm, fp16x2 [node][64] (logical cols)
__device__ uint32_t g_V[MAX_NODES * 64];    // v  = x@W1,      fp16x2 [node][64]

// ---------------- helpers ----------------
__device__ __forceinline__ uint32_t smem_u32(const void* p) {
    uint32_t a;
    asm("{ .reg .u64 t; cvta.to.shared.u64 t, %1; cvt.u32.u64 %0, t; }" : "=r"(a) : "l"(p));
    return a;
}
__device__ __forceinline__ float frelu(float v) { return fmaxf(v, 0.0f); }

__device__ __forceinline__ uint32_t packh2(float a, float b) {
    __half2 h = __floats2half2_rn(a, b);
    return *reinterpret_cast<uint32_t*>(&h);
}
__device__ __forceinline__ float2 unpackh2(uint32_t u) {
    __half2 h = *reinterpret_cast<__half2*>(&u);
    return make_float2(__half2float(__low2half(h)), __half2float(__high2half(h)));
}

// N-permutation: logical output col n -> image row p, so that thread fragments
// (nt=2t,j) + (nt=2t+1,j) cover 4 consecutive logical cols.
// p = (n&64) + 16*t + 8*u + 2*q + s  with  t=(n>>4)&3, q=(n>>2)&3, u=(n>>1)&1, s=n&1
__device__ __forceinline__ int permn(int n) {
    return (n & 64) + (((n >> 4) & 3) << 4) + (((n >> 1) & 1) << 3)
         + (((n >> 2) & 3) << 1) + (n & 1);
}

__device__ __forceinline__ void cp16(uint32_t smem_dst, const void* gsrc) {
    asm volatile("cp.async.cg.shared.global [%0], [%1], 16;"
                 :: "r"(smem_dst), "l"(gsrc) : "memory");
}
__device__ __forceinline__ void cp_commit() {
    asm volatile("cp.async.commit_group;" ::: "memory");
}
__device__ __forceinline__ void cp_wait0() {
    asm volatile("cp.async.wait_group 0;" ::: "memory");
}

__device__ __forceinline__ void ldsm_x4(uint32_t (&r)[4], uint32_t addr) {
    asm volatile("ldmatrix.sync.aligned.m8n8.x4.shared.b16 {%0,%1,%2,%3}, [%4];"
        : "=r"(r[0]), "=r"(r[1]), "=r"(r[2]), "=r"(r[3]) : "r"(addr));
}
__device__ __forceinline__ void ldsm_x2(uint32_t (&r)[2], uint32_t addr) {
    asm volatile("ldmatrix.sync.aligned.m8n8.x2.shared.b16 {%0,%1}, [%2];"
        : "=r"(r[0]), "=r"(r[1]) : "r"(addr));
}
__device__ __forceinline__ void mma16816(float (&d)[4], const uint32_t (&a)[4],
                                         const uint32_t (&b)[2]) {
    asm volatile("mma.sync.aligned.m16n8k16.row.col.f32.f16.f16.f32 "
        "{%0,%1,%2,%3}, {%4,%5,%6,%7}, {%8,%9}, {%0,%1,%2,%3};"
        : "+f"(d[0]), "+f"(d[1]), "+f"(d[2]), "+f"(d[3])
        : "r"(a[0]), "r"(a[1]), "r"(a[2]), "r"(a[3]), "r"(b[0]), "r"(b[1]));
}

// ===== warp GEMM: acc += A(128x128 fp16) @ B^T, warp tile 32x64 =====
__device__ __forceinline__ void do_gemm(uint32_t sb, uint32_t aOff, uint32_t bOff,
                                        float (&acc)[2][8][4],
                                        int wm, int wn, int lane) {
    const int sx = lane & 7;
    const int aR = 32 * wm + sx + ((lane >> 3) & 1) * 8;
    const int aK = (lane >> 4) & 1;
    const int bR = 64 * wn + sx;
    const int bK = (lane >> 3) & 1;
    const uint32_t aBase = sb + aOff + (uint32_t)aR * 256;
    const uint32_t bBase = sb + bOff + (uint32_t)bR * 256;

    #pragma unroll 1
    for (int ks = 0; ks < 8; ks++) {
        uint32_t ah[2][4];
        #pragma unroll
        for (int mt = 0; mt < 2; mt++) {
            uint32_t off = (uint32_t)(mt * 16 * 256) + ((uint32_t)((2 * ks + aK) ^ sx) << 4);
            ldsm_x4(ah[mt], aBase + off);
        }
        #pragma unroll
        for (int nt = 0; nt < 8; nt++) {
            uint32_t off = (uint32_t)(nt * 8 * 256) + ((uint32_t)((2 * ks + bK) ^ sx) << 4);
            uint32_t bh[2];
            ldsm_x2(bh, bBase + off);
            #pragma unroll
            for (int mt = 0; mt < 2; mt++) {
                mma16816(acc[mt][nt], ah[mt], bh);
            }
        }
    }
}

// ================= prep kernel 1: weight images (permuted N) =================
// image row permn(n) holds logical col n; k chunk c placed at (c ^ (row&7))
__global__ void prep_w_kernel(const float* __restrict__ Wm, const float* __restrict__ We) {
    int idx = blockIdx.x * blockDim.x + threadIdx.x;   // < 4*16384
    if (idx >= 65536) return;
    int mat = idx >> 14, e = idx & 16383;
    int n = e >> 7, k = e & 127;
    float v = (mat < 3) ? Wm[(mat * 128 + k) * 128 + n] : We[k * 128 + n];
    int np = permn(n);
    uint32_t pos = (uint32_t)(np * 256 + (((k >> 3) ^ (np & 7)) << 4) + ((k & 7) << 1));
    *(__half*)((char*)g_wimg[mat] + pos) = __float2half_rn(v);
}

// ================= prep kernel 2: U = x@W0 + bm, V = x@W1 (per node) =========
__global__ void __launch_bounds__(THREADS, 2)
prep_uv_kernel(const float* __restrict__ x, const float* __restrict__ bm, int n_nodes)
{
    extern __shared__ char smc[];
    const uint32_t sb = smem_u32(smc);
    const int tid  = threadIdx.x;
    const int wid  = tid >> 5;
    const int lane = tid & 31;
    const int wm   = wid & 3;
    const int wn   = wid >> 2;
    const int t0   = blockIdx.x * ET;
    const int rq   = lane >> 2;
    const int q4   = (lane & 3) * 4;

    // stage W0,W1 images (contiguous in g_wimg)
    #pragma unroll
    for (int it = 0; it < 16; it++) {
        int i = tid + it * THREADS;              // < 4096
        cp16(sb + OFF_WA + i * 16, (const uint4*)g_wimg + i);
    }
    cp_commit();

    // stage x tile fp32 -> fp16 into A
    #pragma unroll 4
    for (int it = 0; it < 8; it++) {
        int i = tid + it * THREADS;
        int e = i >> 4, c = i & 15;
        int node = t0 + e; if (node >= n_nodes) node = n_nodes - 1;
        const float4* s = (const float4*)(x + (long long)node * NH + c * 8);
        float4 fa = __ldg(s), fb = __ldg(s + 1);
        uint4 h;
        h.x = packh2(fa.x, fa.y);
        h.y = packh2(fa.z, fa.w);
        h.z = packh2(fb.x, fb.y);
        h.w = packh2(fb.z, fb.w);
        uint32_t off = (uint32_t)(e * 256 + ((c ^ (e & 7)) << 4));
        *(uint4*)(smc + OFF_A + off) = h;
    }
    cp_wait0();
    __syncthreads();

    float acc[2][8][4];
    #pragma unroll
    for (int i = 0; i < 2; i++)
        #pragma unroll
        for (int j = 0; j < 8; j++)
            #pragma unroll
            for (int q = 0; q < 4; q++) acc[i][j][q] = 0.0f;

    // U = A @ W0^T + bm (logical cols via perm mapping)
    do_gemm(sb, OFF_A, OFF_WA, acc, wm, wn, lane);
    {
        #pragma unroll
        for (int mt = 0; mt < 2; mt++) {
            #pragma unroll
            for (int h = 0; h < 2; h++) {
                int node = t0 + 32 * wm + 16 * mt + 8 * h + rq;
                #pragma unroll
                for (int t = 0; t < 4; t++) {
                    int Lb = 64 * wn + 16 * t + q4;
                    float4 bmv = __ldg((const float4*)(bm + Lb));
                    if (node < n_nodes) {
                        uint2 o;
                        o.x = packh2(acc[mt][2*t  ][2*h+0] + bmv.x,
                                     acc[mt][2*t  ][2*h+1] + bmv.y);
                        o.y = packh2(acc[mt][2*t+1][2*h+0] + bmv.z,
                                     acc[mt][2*t+1][2*h+1] + bmv.w);
                        *(uint2*)(g_U + node * 64 + (Lb >> 1)) = o;
                    }
                    acc[mt][2*t  ][2*h+0] = 0.0f; acc[mt][2*t  ][2*h+1] = 0.0f;
                    acc[mt][2*t+1][2*h+0] = 0.0f; acc[mt][2*t+1][2*h+1] = 0.0f;
                }
            }
        }
    }

    // V = A @ W1^T
    do_gemm(sb, OFF_A, OFF_WB, acc, wm, wn, lane);
    {
        #pragma unroll
        for (int mt = 0; mt < 2; mt++) {
            #pragma unroll
            for (int h = 0; h < 2; h++) {
                int node = t0 + 32 * wm + 16 * mt + 8 * h + rq;
                if (node < n_nodes) {
                    #pragma unroll
                    for (int t = 0; t < 4; t++) {
                        int Lb = 64 * wn + 16 * t + q4;
                        uint2 o;
                        o.x = packh2(acc[mt][2*t  ][2*h+0], acc[mt][2*t  ][2*h+1]);
                        o.y = packh2(acc[mt][2*t+1][2*h+0], acc[mt][2*t+1][2*h+1]);
                        *(uint2*)(g_V + node * 64 + (Lb >> 1)) = o;
                    }
                }
            }
        }
    }
}

// ================= main persistent kernel =================
__global__ void __launch_bounds__(THREADS, 2)
edge_conv_mma(const float* __restrict__ eattr,
              const int*   __restrict__ eidx,
              const float* __restrict__ be,
              float* __restrict__ out,
              int E, int n_nodes)
{
    extern __shared__ char smc[];
    const uint32_t sb = smem_u32(smc);

    const int tid  = threadIdx.x;
    const int wid  = tid >> 5;
    const int lane = tid & 31;
    const int wm   = wid & 3;          // row group (32 edges)
    const int wn   = wid >> 2;         // col group (64 cols)
    const int rq   = lane >> 2;
    const int q4   = (lane & 3) * 4;
    const int ntiles = (E + ET - 1) / ET;

    // ---- prologue: resident W2 + W3 images ----
    #pragma unroll
    for (int it = 0; it < 16; it++) {
        int i = tid + it * THREADS;              // < 4096
        cp16(sb + OFF_WA + i * 16, (const uint4*)g_wimg + 2 * 2048 + i);
    }
    cp_commit();

    for (int tile = blockIdx.x; tile < ntiles; tile += gridDim.x) {
        const long long e0 = (long long)tile * ET;

        // --- stage eattr (fp32 -> fp16) into A ---
        #pragma unroll 4
        for (int it = 0; it < 8; it++) {
            int i = tid + it * THREADS;
            int e = i >> 4, c = i & 15;
            long long ge = e0 + e; if (ge >= E) ge = E - 1;
            const float4* s = (const float4*)(eattr + ge * NH + c * 8);
            float4 fa = __ldg(s), fb = __ldg(s + 1);
            uint4 h;
            h.x = packh2(fa.x, fa.y);
            h.y = packh2(fa.z, fa.w);
            h.z = packh2(fb.x, fb.y);
            h.w = packh2(fb.z, fb.w);
            uint32_t off = (uint32_t)(e * 256 + ((c ^ (e & 7)) << 4));
            *(uint4*)(smc + OFF_A + off) = h;
        }
        cp_wait0();        // weights resident (no-op after first tile)
        __syncthreads();

        // --- hoist idx loads: consumed in epi1, latency hidden under GEMM1 ---
        int rn4[4], cn4[4];
        #pragma unroll
        for (int mt = 0; mt < 2; mt++) {
            #pragma unroll
            for (int h = 0; h < 2; h++) {
                int row = 32 * wm + 16 * mt + 8 * h + rq;
                long long ge = e0 + row; if (ge >= E) ge = E - 1;
                int rn = __ldg(eidx + ge);
                int cn = __ldg(eidx + (long long)E + ge);
                rn4[mt * 2 + h] = min(max(rn, 0), n_nodes - 1);
                cn4[mt * 2 + h] = min(max(cn, 0), n_nodes - 1);
            }
        }

        float acc[2][8][4];
        #pragma unroll
        for (int i = 0; i < 2; i++)
            #pragma unroll
            for (int j = 0; j < 8; j++)
                #pragma unroll
                for (int q = 0; q < 4; q++) acc[i][j][q] = 0.0f;

        // =========== GEMM 1: ea @ W2 ===========
        do_gemm(sb, OFF_A, OFF_WA, acc, wm, wn, lane);
        __syncthreads();   // A readers done before epi1 RMW

        // ==== epilogue 1: ea2 = ea + relu(u[row] + v[col] + ea@W2), RMW A ====
        {
            #pragma unroll
            for (int mt = 0; mt < 2; mt++) {
                #pragma unroll
                for (int h = 0; h < 2; h++) {
                    int row = 32 * wm + 16 * mt + 8 * h + rq;
                    const uint32_t* urow = g_U + rn4[mt * 2 + h] * 64;
                    const uint32_t* vrow = g_V + cn4[mt * 2 + h] * 64;
                    #pragma unroll
                    for (int t = 0; t < 4; t++) {
                        int Lb = 64 * wn + 16 * t + q4;
                        uint2 uu = *(const uint2*)(urow + (Lb >> 1));
                        uint2 vv = *(const uint2*)(vrow + (Lb >> 1));
                        uint32_t addr = (uint32_t)(row * 256 +
                                        (((Lb >> 3) ^ (row & 7)) << 4) + ((Lb & 7) << 1));
                        uint2 ea = *(uint2*)(smc + OFF_A + addr);
                        float2 u0 = unpackh2(uu.x), u1 = unpackh2(uu.y);
                        float2 v0 = unpackh2(vv.x), v1 = unpackh2(vv.y);
                        float2 ev0 = unpackh2(ea.x), ev1 = unpackh2(ea.y);
                        float r0 = ev0.x + frelu(acc[mt][2*t  ][2*h+0] + u0.x + v0.x);
                        float r1 = ev0.y + frelu(acc[mt][2*t  ][2*h+1] + u0.y + v0.y);
                        float r2 = ev1.x + frelu(acc[mt][2*t+1][2*h+0] + u1.x + v1.x);
                        float r3 = ev1.y + frelu(acc[mt][2*t+1][2*h+1] + u1.y + v1.y);
                        uint2 o; o.x = packh2(r0, r1); o.y = packh2(r2, r3);
                        *(uint2*)(smc + OFF_A + addr) = o;
                        acc[mt][2*t  ][2*h+0] = 0.0f; acc[mt][2*t  ][2*h+1] = 0.0f;
                        acc[mt][2*t+1][2*h+0] = 0.0f; acc[mt][2*t+1][2*h+1] = 0.0f;
                    }
                }
            }
        }
        __syncthreads();   // ea2 complete across warps

        // =========== GEMM 2: ea2 @ W_edge ===========
        do_gemm(sb, OFF_A, OFF_WB, acc, wm, wn, lane);
        __syncthreads();   // A consumed -> next tile may restage

        // =========== epilogue 2: out = relu(acc + be), float4 stores ===========
        {
            #pragma unroll
            for (int mt = 0; mt < 2; mt++) {
                #pragma unroll
                for (int h = 0; h < 2; h++) {
                    int row = 32 * wm + 16 * mt + 8 * h + rq;
                    long long ge = e0 + row;
                    if (ge < E) {
                        #pragma unroll
                        for (int t = 0; t < 4; t++) {
                            int Lb = 64 * wn + 16 * t + q4;
                            float4 bev = __ldg((const float4*)(be + Lb));
                            float4 o;
                            o.x = frelu(acc[mt][2*t  ][2*h+0] + bev.x);
                            o.y = frelu(acc[mt][2*t  ][2*h+1] + bev.y);
                            o.z = frelu(acc[mt][2*t+1][2*h+0] + bev.z);
                            o.w = frelu(acc[mt][2*t+1][2*h+1] + bev.w);
                            *(float4*)(out + ge * NH + Lb) = o;
                        }
                    }
                }
            }
        }
    }
}

// ================= host =================
extern "C" void kernel_launch(void* const* d_in, const int* in_sizes, int n_in,
                              void* d_out, int out_size)
{
    const float* x     = (const float*)d_in[0];
    const float* eattr = (const float*)d_in[1];
    const int*   eidx  = (const int*)d_in[2];   // int32 (JAX canonicalizes int64->int32)
    const float* Wm    = (const float*)d_in[3];
    const float* bm    = (const float*)d_in[4];
    const float* We    = (const float*)d_in[5];
    const float* be    = (const float*)d_in[6];
    float*       out   = (float*)d_out;

    const int E  = in_sizes[2] / 2;
    int n_nodes  = in_sizes[0] / NH;
    if (n_nodes > MAX_NODES) n_nodes = MAX_NODES;

    prep_w_kernel<<<(65536 + 255) / 256, 256>>>(Wm, We);

    cudaFuncSetAttribute(prep_uv_kernel,
                         cudaFuncAttributeMaxDynamicSharedMemorySize, SMEM_TOTAL);
    cudaFuncSetAttribute(edge_conv_mma,
                         cudaFuncAttributeMaxDynamicSharedMemorySize, SMEM_TOTAL);

    const int ntileN = (n_nodes + ET - 1) / ET;
    prep_uv_kernel<<<ntileN, THREADS, SMEM_TOTAL>>>(x, bm, n_nodes);

    int nsm = 148;
    cudaDeviceGetAttribute(&nsm, cudaDevAttrMultiProcessorCount, 0);
    const int ntiles = (E + ET - 1) / ET;
    int grid = 2 * nsm < ntiles ? 2 * nsm : ntiles;

    edge_conv_mma<<<grid, THREADS, SMEM_TOTAL>>>(eattr, eidx, be, out, E, n_nodes);
}

// round 16
// speedup vs baseline: 1.4940x; 1.0127x over previous
#include <cuda_runtime.h>
#include <cuda_fp16.h>
#include <cstdint>

#define NH       128
#define ET       128          // edges (or nodes) per tile
#define THREADS  256          // 8 warps, 32x64 warp tiles

// ---------------- smem layout (bytes): A + two resident B images ----------------
#define OFF_A    0             // 128 rows x 256B (fp16)
#define OFF_WA   32768
#define OFF_WB   65536
#define SMEM_TOTAL 98304       // 96KB -> 2 CTAs/SM

#define MAX_NODES 131072

// ---------------- device scratch (no allocs allowed) ----------------
__device__ uint4    g_wimg[4][2048];        // B'[n][k] fp16, swizzled+permuted 32KB images
__device__ uint32_t g_U[MAX_NODES * 64];    // u' = x@W0 + bm, fp16x2 [node][64] (logical cols)
__device__ uint32_t g_V[MAX_NODES * 64];    // v  = x@W1,      fp16x2 [node][64]

// ---------------- helpers ----------------
__device__ __forceinline__ uint32_t smem_u32(const void* p) {
    uint32_t a;
    asm("{ .reg .u64 t; cvta.to.shared.u64 t, %1; cvt.u32.u64 %0, t; }" : "=r"(a) : "l"(p));
    return a;
}
__device__ __forceinline__ float frelu(float v) { return fmaxf(v, 0.0f); }

__device__ __forceinline__ uint32_t packh2(float a, float b) {
    __half2 h = __floats2half2_rn(a, b);
    return *reinterpret_cast<uint32_t*>(&h);
}
__device__ __forceinline__ float2 unpackh2(uint32_t u) {
    __half2 h = *reinterpret_cast<__half2*>(&u);
    return make_float2(__half2float(__low2half(h)), __half2float(__high2half(h)));
}

// N-permutation: logical output col n -> image row p, so that thread fragments
// (nt=2t,j) + (nt=2t+1,j) cover 4 consecutive logical cols.
__device__ __forceinline__ int permn(int n) {
    return (n & 64) + (((n >> 4) & 3) << 4) + (((n >> 1) & 1) << 3)
         + (((n >> 2) & 3) << 1) + (n & 1);
}

__device__ __forceinline__ void cp16(uint32_t smem_dst, const void* gsrc) {
    asm volatile("cp.async.cg.shared.global [%0], [%1], 16;"
                 :: "r"(smem_dst), "l"(gsrc) : "memory");
}
__device__ __forceinline__ void cp_commit() {
    asm volatile("cp.async.commit_group;" ::: "memory");
}
__device__ __forceinline__ void cp_wait0() {
    asm volatile("cp.async.wait_group 0;" ::: "memory");
}

__device__ __forceinline__ void ldsm_x4(uint32_t (&r)[4], uint32_t addr) {
    asm volatile("ldmatrix.sync.aligned.m8n8.x4.shared.b16 {%0,%1,%2,%3}, [%4];"
        : "=r"(r[0]), "=r"(r[1]), "=r"(r[2]), "=r"(r[3]) : "r"(addr));
}
__device__ __forceinline__ void mma16816(float (&d)[4], const uint32_t (&a)[4],
                                         const uint32_t b0, const uint32_t b1) {
    asm volatile("mma.sync.aligned.m16n8k16.row.col.f32.f16.f16.f32 "
        "{%0,%1,%2,%3}, {%4,%5,%6,%7}, {%8,%9}, {%0,%1,%2,%3};"
        : "+f"(d[0]), "+f"(d[1]), "+f"(d[2]), "+f"(d[3])
        : "r"(a[0]), "r"(a[1]), "r"(a[2]), "r"(a[3]), "r"(b0), "r"(b1));
}

// ===== warp GEMM: acc += A(128x128 fp16) @ B^T, warp tile 32x64 =====
// B fetched two nt-tiles per ldsm.x4 (lanes 16-31 address tile nt+1).
__device__ __forceinline__ void do_gemm(uint32_t sb, uint32_t aOff, uint32_t bOff,
                                        float (&acc)[2][8][4],
                                        int wm, int wn, int lane) {
    const int sx = lane & 7;
    const int aR = 32 * wm + sx + ((lane >> 3) & 1) * 8;
    const int aK = (lane >> 4) & 1;
    const int bK = (lane >> 3) & 1;      // k half: 0,1,0,1 per 8-lane group
    const int bT = (lane >> 4) & 1;      // which nt of the pair
    const uint32_t aBase = sb + aOff + (uint32_t)aR * 256;
    const uint32_t bBase = sb + bOff + (uint32_t)(64 * wn + sx + bT * 8) * 256;

    #pragma unroll 1
    for (int ks = 0; ks < 8; ks++) {
        uint32_t ah[2][4];
        #pragma unroll
        for (int mt = 0; mt < 2; mt++) {
            uint32_t off = (uint32_t)(mt * 16 * 256) + ((uint32_t)((2 * ks + aK) ^ sx) << 4);
            ldsm_x4(ah[mt], aBase + off);
        }
        #pragma unroll
        for (int ntp = 0; ntp < 4; ntp++) {
            uint32_t off = (uint32_t)(ntp * 16 * 256) + ((uint32_t)((2 * ks + bK) ^ sx) << 4);
            uint32_t bh4[4];
            ldsm_x4(bh4, bBase + off);
            #pragma unroll
            for (int mt = 0; mt < 2; mt++) {
                mma16816(acc[mt][2 * ntp    ], ah[mt], bh4[0], bh4[1]);
                mma16816(acc[mt][2 * ntp + 1], ah[mt], bh4[2], bh4[3]);
            }
        }
    }
}

// ================= prep kernel 1: weight images (permuted N) =================
__global__ void prep_w_kernel(const float* __restrict__ Wm, const float* __restrict__ We) {
    int idx = blockIdx.x * blockDim.x + threadIdx.x;   // < 4*16384
    if (idx >= 65536) return;
    int mat = idx >> 14, e = idx & 16383;
    int n = e >> 7, k = e & 127;
    float v = (mat < 3) ? Wm[(mat * 128 + k) * 128 + n] : We[k * 128 + n];
    int np = permn(n);
    uint32_t pos = (uint32_t)(np * 256 + (((k >> 3) ^ (np & 7)) << 4) + ((k & 7) << 1));
    *(__half*)((char*)g_wimg[mat] + pos) = __float2half_rn(v);
}

// ====== prep kernel 2 (persistent): U = x@W0 + bm, V = x@W1 (per node) ======
__global__ void __launch_bounds__(THREADS, 2)
prep_uv_kernel(const float* __restrict__ x, const float* __restrict__ bm, int n_nodes)
{
    extern __shared__ char smc[];
    const uint32_t sb = smem_u32(smc);
    const int tid  = threadIdx.x;
    const int wid  = tid >> 5;
    const int lane = tid & 31;
    const int wm   = wid & 3;
    const int wn   = wid >> 2;
    const int rq   = lane >> 2;
    const int q4   = (lane & 3) * 4;
    const int ntileN = (n_nodes + ET - 1) / ET;

    // stage W0,W1 images once (contiguous in g_wimg)
    #pragma unroll
    for (int it = 0; it < 16; it++) {
        int i = tid + it * THREADS;              // < 4096
        cp16(sb + OFF_WA + i * 16, (const uint4*)g_wimg + i);
    }
    cp_commit();

    for (int tile = blockIdx.x; tile < ntileN; tile += gridDim.x) {
        const int t0 = tile * ET;

        // stage x tile fp32 -> fp16 into A
        #pragma unroll 4
        for (int it = 0; it < 8; it++) {
            int i = tid + it * THREADS;
            int e = i >> 4, c = i & 15;
            int node = t0 + e; if (node >= n_nodes) node = n_nodes - 1;
            const float4* s = (const float4*)(x + (long long)node * NH + c * 8);
            float4 fa = __ldg(s), fb = __ldg(s + 1);
            uint4 h;
            h.x = packh2(fa.x, fa.y);
            h.y = packh2(fa.z, fa.w);
            h.z = packh2(fb.x, fb.y);
            h.w = packh2(fb.z, fb.w);
            uint32_t off = (uint32_t)(e * 256 + ((c ^ (e & 7)) << 4));
            *(uint4*)(smc + OFF_A + off) = h;
        }
        cp_wait0();        // weights resident (no-op after first tile)
        __syncthreads();

        float acc[2][8][4];
        #pragma unroll
        for (int i = 0; i < 2; i++)
            #pragma unroll
            for (int j = 0; j < 8; j++)
                #pragma unroll
                for (int q = 0; q < 4; q++) acc[i][j][q] = 0.0f;

        // U = A @ W0^T + bm
        do_gemm(sb, OFF_A, OFF_WA, acc, wm, wn, lane);
        {
            #pragma unroll
            for (int mt = 0; mt < 2; mt++) {
                #pragma unroll
                for (int h = 0; h < 2; h++) {
                    int node = t0 + 32 * wm + 16 * mt + 8 * h + rq;
                    #pragma unroll
                    for (int t = 0; t < 4; t++) {
                        int Lb = 64 * wn + 16 * t + q4;
                        float4 bmv = __ldg((const float4*)(bm + Lb));
                        if (node < n_nodes) {
                            uint2 o;
                            o.x = packh2(acc[mt][2*t  ][2*h+0] + bmv.x,
                                         acc[mt][2*t  ][2*h+1] + bmv.y);
                            o.y = packh2(acc[mt][2*t+1][2*h+0] + bmv.z,
                                         acc[mt][2*t+1][2*h+1] + bmv.w);
                            *(uint2*)(g_U + node * 64 + (Lb >> 1)) = o;
                        }
                        acc[mt][2*t  ][2*h+0] = 0.0f; acc[mt][2*t  ][2*h+1] = 0.0f;
                        acc[mt][2*t+1][2*h+0] = 0.0f; acc[mt][2*t+1][2*h+1] = 0.0f;
                    }
                }
            }
        }

        // V = A @ W1^T (A unchanged; no sync needed between the two gemms)
        do_gemm(sb, OFF_A, OFF_WB, acc, wm, wn, lane);
        {
            #pragma unroll
            for (int mt = 0; mt < 2; mt++) {
                #pragma unroll
                for (int h = 0; h < 2; h++) {
                    int node = t0 + 32 * wm + 16 * mt + 8 * h + rq;
                    if (node < n_nodes) {
                        #pragma unroll
                        for (int t = 0; t < 4; t++) {
                            int Lb = 64 * wn + 16 * t + q4;
                            uint2 o;
                            o.x = packh2(acc[mt][2*t  ][2*h+0], acc[mt][2*t  ][2*h+1]);
                            o.y = packh2(acc[mt][2*t+1][2*h+0], acc[mt][2*t+1][2*h+1]);
                            *(uint2*)(g_V + node * 64 + (Lb >> 1)) = o;
                        }
                    }
                }
            }
        }
        __syncthreads();   // gemm V readers done before next tile restages A
    }
}

// ================= main persistent kernel =================
__global__ void __launch_bounds__(THREADS, 2)
edge_conv_mma(const float* __restrict__ eattr,
              const int*   __restrict__ eidx,
              const float* __restrict__ be,
              float* __restrict__ out,
              int E, int n_nodes)
{
    extern __shared__ char smc[];
    const uint32_t sb = smem_u32(smc);

    const int tid  = threadIdx.x;
    const int wid  = tid >> 5;
    const int lane = tid & 31;
    const int wm   = wid & 3;          // row group (32 edges)
    const int wn   = wid >> 2;         // col group (64 cols)
    const int rq   = lane >> 2;
    const int q4   = (lane & 3) * 4;
    const int ntiles = (E + ET - 1) / ET;

    // ---- prologue: resident W2 + W3 images ----
    #pragma unroll
    for (int it = 0; it < 16; it++) {
        int i = tid + it * THREADS;              // < 4096
        cp16(sb + OFF_WA + i * 16, (const uint4*)g_wimg + 2 * 2048 + i);
    }
    cp_commit();

    for (int tile = blockIdx.x; tile < ntiles; tile += gridDim.x) {
        const long long e0 = (long long)tile * ET;

        // --- stage eattr (fp32 -> fp16) into A ---
        #pragma unroll 4
        for (int it = 0; it < 8; it++) {
            int i = tid + it * THREADS;
            int e = i >> 4, c = i & 15;
            long long ge = e0 + e; if (ge >= E) ge = E - 1;
            const float4* s = (const float4*)(eattr + ge * NH + c * 8);
            float4 fa = __ldg(s), fb = __ldg(s + 1);
            uint4 h;
            h.x = packh2(fa.x, fa.y);
            h.y = packh2(fa.z, fa.w);
            h.z = packh2(fb.x, fb.y);
            h.w = packh2(fb.z, fb.w);
            uint32_t off = (uint32_t)(e * 256 + ((c ^ (e & 7)) << 4));
            *(uint4*)(smc + OFF_A + off) = h;
        }
        cp_wait0();        // weights resident (no-op after first tile)
        __syncthreads();   // S1

        // --- hoist idx loads (latency hides under GEMM1) ---
        int rn4[4], cn4[4];
        #pragma unroll
        for (int mt = 0; mt < 2; mt++) {
            #pragma unroll
            for (int h = 0; h < 2; h++) {
                int row = 32 * wm + 16 * mt + 8 * h + rq;
                long long ge = e0 + row; if (ge >= E) ge = E - 1;
                int rn = __ldg(eidx + ge);
                int cn = __ldg(eidx + (long long)E + ge);
                rn4[mt * 2 + h] = min(max(rn, 0), n_nodes - 1);
                cn4[mt * 2 + h] = min(max(cn, 0), n_nodes - 1);
            }
        }

        float acc[2][8][4];
        #pragma unroll
        for (int i = 0; i < 2; i++)
            #pragma unroll
            for (int j = 0; j < 8; j++)
                #pragma unroll
                for (int q = 0; q < 4; q++) acc[i][j][q] = 0.0f;

        // =========== GEMM 1: ea @ W2 ===========
        do_gemm(sb, OFF_A, OFF_WA, acc, wm, wn, lane);

        // --- prefetch u/v batch 0 (latency hides under sync wait) ---
        uint2 puu[4], pvv[4];
        {
            const uint32_t* urow = g_U + rn4[0] * 64;
            const uint32_t* vrow = g_V + cn4[0] * 64;
            #pragma unroll
            for (int t = 0; t < 4; t++) {
                int Lb = 64 * wn + 16 * t + q4;
                puu[t] = *(const uint2*)(urow + (Lb >> 1));
                pvv[t] = *(const uint2*)(vrow + (Lb >> 1));
            }
        }
        __syncthreads();   // S2: A readers done before epi1 RMW

        // ==== epilogue 1: ea2 = ea + relu(u[row] + v[col] + ea@W2), RMW A ====
        // u/v software-pipelined: batch i consumed while batch i+1 flies.
        #pragma unroll
        for (int i = 0; i < 4; i++) {
            const int mt = i >> 1, h = i & 1;
            uint2 cuu[4], cvv[4];
            #pragma unroll
            for (int t = 0; t < 4; t++) { cuu[t] = puu[t]; cvv[t] = pvv[t]; }
            if (i < 3) {
                const uint32_t* urow = g_U + rn4[i + 1] * 64;
                const uint32_t* vrow = g_V + cn4[i + 1] * 64;
                #pragma unroll
                for (int t = 0; t < 4; t++) {
                    int Lb = 64 * wn + 16 * t + q4;
                    puu[t] = *(const uint2*)(urow + (Lb >> 1));
                    pvv[t] = *(const uint2*)(vrow + (Lb >> 1));
                }
            }
            const int row = 32 * wm + 16 * mt + 8 * h + rq;
            #pragma unroll
            for (int t = 0; t < 4; t++) {
                int Lb = 64 * wn + 16 * t + q4;
                uint32_t addr = (uint32_t)(row * 256 +
                                (((Lb >> 3) ^ (row & 7)) << 4) + ((Lb & 7) << 1));
                uint2 ea = *(uint2*)(smc + OFF_A + addr);
                float2 u0 = unpackh2(cuu[t].x), u1 = unpackh2(cuu[t].y);
                float2 v0 = unpackh2(cvv[t].x), v1 = unpackh2(cvv[t].y);
                float2 ev0 = unpackh2(ea.x), ev1 = unpackh2(ea.y);
                float r0 = ev0.x + frelu(acc[mt][2*t  ][2*h+0] + u0.x + v0.x);
                float r1 = ev0.y + frelu(acc[mt][2*t  ][2*h+1] + u0.y + v0.y);
                float r2 = ev1.x + frelu(acc[mt][2*t+1][2*h+0] + u1.x + v1.x);
                float r3 = ev1.y + frelu(acc[mt][2*t+1][2*h+1] + u1.y + v1.y);
                uint2 o; o.x = packh2(r0, r1); o.y = packh2(r2, r3);
                *(uint2*)(smc + OFF_A + addr) = o;
                acc[mt][2*t  ][2*h+0] = 0.0f; acc[mt][2*t  ][2*h+1] = 0.0f;
                acc[mt][2*t+1][2*h+0] = 0.0f; acc[mt][2*t+1][2*h+1] = 0.0f;
            }
        }
        __syncthreads();   // S3: ea2 complete across warps

        // =========== GEMM 2: ea2 @ W_edge ===========
        do_gemm(sb, OFF_A, OFF_WB, acc, wm, wn, lane);

        // ===== epilogue 2 BEFORE S4 (no smem hazard: acc -> gmem only) =====
        {
            #pragma unroll
            for (int mt = 0; mt < 2; mt++) {
                #pragma unroll
                for (int h = 0; h < 2; h++) {
                    int row = 32 * wm + 16 * mt + 8 * h + rq;
                    long long ge = e0 + row;
                    if (ge < E) {
                        #pragma unroll
                        for (int t = 0; t < 4; t++) {
                            int Lb = 64 * wn + 16 * t + q4;
                            float4 bev = __ldg((const float4*)(be + Lb));
                            float4 o;
                            o.x = frelu(acc[mt][2*t  ][2*h+0] + bev.x);
                            o.y = frelu(acc[mt][2*t  ][2*h+1] + bev.y);
                            o.z = frelu(acc[mt][2*t+1][2*h+0] + bev.z);
                            o.w = frelu(acc[mt][2*t+1][2*h+1] + bev.w);
                            *(float4*)(out + ge * NH + Lb) = o;
                        }
                    }
                }
            }
        }
        __syncthreads();   // S4: A consumed -> next tile may restage
    }
}

// ================= host =================
extern "C" void kernel_launch(void* const* d_in, const int* in_sizes, int n_in,
                              void* d_out, int out_size)
{
    const float* x     = (const float*)d_in[0];
    const float* eattr = (const float*)d_in[1];
    const int*   eidx  = (const int*)d_in[2];   // int32 (JAX canonicalizes int64->int32)
    const float* Wm    = (const float*)d_in[3];
    const float* bm    = (const float*)d_in[4];
    const float* We    = (const float*)d_in[5];
    const float* be    = (const float*)d_in[6];
    float*       out   = (float*)d_out;

    const int E  = in_sizes[2] / 2;
    int n_nodes  = in_sizes[0] / NH;
    if (n_nodes > MAX_NODES) n_nodes = MAX_NODES;

    prep_w_kernel<<<(65536 + 255) / 256, 256>>>(Wm, We);

    cudaFuncSetAttribute(prep_uv_kernel,
                         cudaFuncAttributeMaxDynamicSharedMemorySize, SMEM_TOTAL);
    cudaFuncSetAttribute(edge_conv_mma,
                         cudaFuncAttributeMaxDynamicSharedMemorySize, SMEM_TOTAL);

    int nsm = 148;
    cudaDeviceGetAttribute(&nsm, cudaDevAttrMultiProcessorCount, 0);

    const int ntileN = (n_nodes + ET - 1) / ET;
    int gridN = 2 * nsm < ntileN ? 2 * nsm : ntileN;
    prep_uv_kernel<<<gridN, THREADS, SMEM_TOTAL>>>(x, bm, n_nodes);

    const int ntiles = (E + ET - 1) / ET;
    int grid = 2 * nsm < ntiles ? 2 * nsm : ntiles;
    edge_conv_mma<<<grid, THREADS, SMEM_TOTAL>>>(eattr, eidx, be, out, E, n_nodes);
}

// round 17
// speedup vs baseline: 1.5431x; 1.0329x over previous
#include <cuda_runtime.h>
#include <cuda_fp16.h>
#include <cstdint>

#define NH       128
#define ET       64           // edges per half-CTA tile
#define THREADS  256          // 2 groups x 4 warps, 32x64 warp tiles

// ---------------- smem layout (bytes): 2 A half-tiles + two resident B images --
#define OFF_A    0             // group g at OFF_A + g*16384 (64 rows x 256B fp16)
#define OFF_WA   32768
#define OFF_WB   65536
#define SMEM_TOTAL 98304       // 96KB -> 2 CTAs/SM

#define MAX_NODES 131072

// ---------------- device scratch (no allocs allowed) ----------------
__device__ uint4    g_wimg[4][2048];        // B'[n][k] fp16, swizzled+permuted 32KB images
__device__ uint32_t g_U[MAX_NODES * 64];    // u' = x@W0 + bm, fp16x2 [node][64] (logical cols)
__device__ uint32_t g_V[MAX_NODES * 64];    // v  = x@W1,      fp16x2 [node][64]

// ---------------- helpers ----------------
__device__ __forceinline__ uint32_t smem_u32(const void* p) {
    uint32_t a;
    asm("{ .reg .u64 t; cvta.to.shared.u64 t, %1; cvt.u32.u64 %0, t; }" : "=r"(a) : "l"(p));
    return a;
}
__device__ __forceinline__ float frelu(float v) { return fmaxf(v, 0.0f); }

__device__ __forceinline__ uint32_t packh2(float a, float b) {
    __half2 h = __floats2half2_rn(a, b);
    return *reinterpret_cast<uint32_t*>(&h);
}
__device__ __forceinline__ float2 unpackh2(uint32_t u) {
    __half2 h = *reinterpret_cast<__half2*>(&u);
    return make_float2(__half2float(__low2half(h)), __half2float(__high2half(h)));
}

// N-permutation: logical output col n -> image row p (epilogue vectorization).
__device__ __forceinline__ int permn(int n) {
    return (n & 64) + (((n >> 4) & 3) << 4) + (((n >> 1) & 1) << 3)
         + (((n >> 2) & 3) << 1) + (n & 1);
}

__device__ __forceinline__ void cp16(uint32_t smem_dst, const void* gsrc) {
    asm volatile("cp.async.cg.shared.global [%0], [%1], 16;"
                 :: "r"(smem_dst), "l"(gsrc) : "memory");
}
__device__ __forceinline__ void cp_commit() {
    asm volatile("cp.async.commit_group;" ::: "memory");
}
__device__ __forceinline__ void cp_wait0() {
    asm volatile("cp.async.wait_group 0;" ::: "memory");
}
// named barrier: 128 threads (one 4-warp group)
__device__ __forceinline__ void barg(int id) {
    asm volatile("bar.sync %0, 128;" :: "r"(id) : "memory");
}

__device__ __forceinline__ void ldsm_x4(uint32_t (&r)[4], uint32_t addr) {
    asm volatile("ldmatrix.sync.aligned.m8n8.x4.shared.b16 {%0,%1,%2,%3}, [%4];"
        : "=r"(r[0]), "=r"(r[1]), "=r"(r[2]), "=r"(r[3]) : "r"(addr));
}
__device__ __forceinline__ void mma16816(float (&d)[4], const uint32_t (&a)[4],
                                         const uint32_t b0, const uint32_t b1) {
    asm volatile("mma.sync.aligned.m16n8k16.row.col.f32.f16.f16.f32 "
        "{%0,%1,%2,%3}, {%4,%5,%6,%7}, {%8,%9}, {%0,%1,%2,%3};"
        : "+f"(d[0]), "+f"(d[1]), "+f"(d[2]), "+f"(d[3])
        : "r"(a[0]), "r"(a[1]), "r"(a[2]), "r"(a[3]), "r"(b0), "r"(b1));
}

// ===== warp GEMM: acc += A(rows x128 fp16) @ B^T, warp tile 32x64 =====
// B fetched two nt-tiles per ldsm.x4 (lanes 16-31 address tile nt+1).
__device__ __forceinline__ void do_gemm(uint32_t sb, uint32_t aOff, uint32_t bOff,
                                        float (&acc)[2][8][4],
                                        int wm, int wn, int lane) {
    const int sx = lane & 7;
    const int aR = 32 * wm + sx + ((lane >> 3) & 1) * 8;
    const int aK = (lane >> 4) & 1;
    const int bK = (lane >> 3) & 1;
    const int bT = (lane >> 4) & 1;
    const uint32_t aBase = sb + aOff + (uint32_t)aR * 256;
    const uint32_t bBase = sb + bOff + (uint32_t)(64 * wn + sx + bT * 8) * 256;

    #pragma unroll 1
    for (int ks = 0; ks < 8; ks++) {
        uint32_t ah[2][4];
        #pragma unroll
        for (int mt = 0; mt < 2; mt++) {
            uint32_t off = (uint32_t)(mt * 16 * 256) + ((uint32_t)((2 * ks + aK) ^ sx) << 4);
            ldsm_x4(ah[mt], aBase + off);
        }
        #pragma unroll
        for (int ntp = 0; ntp < 4; ntp++) {
            uint32_t off = (uint32_t)(ntp * 16 * 256) + ((uint32_t)((2 * ks + bK) ^ sx) << 4);
            uint32_t bh4[4];
            ldsm_x4(bh4, bBase + off);
            #pragma unroll
            for (int mt = 0; mt < 2; mt++) {
                mma16816(acc[mt][2 * ntp    ], ah[mt], bh4[0], bh4[1]);
                mma16816(acc[mt][2 * ntp + 1], ah[mt], bh4[2], bh4[3]);
            }
        }
    }
}

// ================= prep kernel 1: weight images (permuted N) =================
__global__ void prep_w_kernel(const float* __restrict__ Wm, const float* __restrict__ We) {
    int idx = blockIdx.x * blockDim.x + threadIdx.x;   // < 4*16384
    if (idx >= 65536) return;
    int mat = idx >> 14, e = idx & 16383;
    int n = e >> 7, k = e & 127;
    float v = (mat < 3) ? Wm[(mat * 128 + k) * 128 + n] : We[k * 128 + n];
    int np = permn(n);
    uint32_t pos = (uint32_t)(np * 256 + (((k >> 3) ^ (np & 7)) << 4) + ((k & 7) << 1));
    *(__half*)((char*)g_wimg[mat] + pos) = __float2half_rn(v);
}

// ====== prep kernel 2 (persistent): U = x@W0 + bm, V = x@W1 (per node) ======
// Uses the two A half-buffers as one 128-row tile (wm 0..3 across both).
__global__ void __launch_bounds__(THREADS, 2)
prep_uv_kernel(const float* __restrict__ x, const float* __restrict__ bm, int n_nodes)
{
    extern __shared__ char smc[];
    const uint32_t sb = smem_u32(smc);
    const int tid  = threadIdx.x;
    const int wid  = tid >> 5;
    const int lane = tid & 31;
    const int wm   = wid & 3;
    const int wn   = wid >> 2;
    const int rq   = lane >> 2;
    const int q4   = (lane & 3) * 4;
    const int ntileN = (n_nodes + 127) / 128;

    #pragma unroll
    for (int it = 0; it < 16; it++) {
        int i = tid + it * THREADS;              // < 4096
        cp16(sb + OFF_WA + i * 16, (const uint4*)g_wimg + i);
    }
    cp_commit();
    cp_wait0();
    __syncthreads();

    for (int tile = blockIdx.x; tile < ntileN; tile += gridDim.x) {
        const int t0 = tile * 128;

        #pragma unroll 4
        for (int it = 0; it < 8; it++) {
            int i = tid + it * THREADS;
            int e = i >> 4, c = i & 15;
            int node = t0 + e; if (node >= n_nodes) node = n_nodes - 1;
            const float4* s = (const float4*)(x + (long long)node * NH + c * 8);
            float4 fa = __ldg(s), fb = __ldg(s + 1);
            uint4 h;
            h.x = packh2(fa.x, fa.y);
            h.y = packh2(fa.z, fa.w);
            h.z = packh2(fb.x, fb.y);
            h.w = packh2(fb.z, fb.w);
            uint32_t off = (uint32_t)(e * 256 + ((c ^ (e & 7)) << 4));
            *(uint4*)(smc + OFF_A + off) = h;
        }
        __syncthreads();

        float acc[2][8][4];
        #pragma unroll
        for (int i = 0; i < 2; i++)
            #pragma unroll
            for (int j = 0; j < 8; j++)
                #pragma unroll
                for (int q = 0; q < 4; q++) acc[i][j][q] = 0.0f;

        do_gemm(sb, OFF_A, OFF_WA, acc, wm, wn, lane);
        {
            #pragma unroll
            for (int mt = 0; mt < 2; mt++) {
                #pragma unroll
                for (int h = 0; h < 2; h++) {
                    int node = t0 + 32 * wm + 16 * mt + 8 * h + rq;
                    #pragma unroll
                    for (int t = 0; t < 4; t++) {
                        int Lb = 64 * wn + 16 * t + q4;
                        float4 bmv = __ldg((const float4*)(bm + Lb));
                        if (node < n_nodes) {
                            uint2 o;
                            o.x = packh2(acc[mt][2*t  ][2*h+0] + bmv.x,
                                         acc[mt][2*t  ][2*h+1] + bmv.y);
                            o.y = packh2(acc[mt][2*t+1][2*h+0] + bmv.z,
                                         acc[mt][2*t+1][2*h+1] + bmv.w);
                            *(uint2*)(g_U + node * 64 + (Lb >> 1)) = o;
                        }
                        acc[mt][2*t  ][2*h+0] = 0.0f; acc[mt][2*t  ][2*h+1] = 0.0f;
                        acc[mt][2*t+1][2*h+0] = 0.0f; acc[mt][2*t+1][2*h+1] = 0.0f;
                    }
                }
            }
        }

        do_gemm(sb, OFF_A, OFF_WB, acc, wm, wn, lane);
        {
            #pragma unroll
            for (int mt = 0; mt < 2; mt++) {
                #pragma unroll
                for (int h = 0; h < 2; h++) {
                    int node = t0 + 32 * wm + 16 * mt + 8 * h + rq;
                    if (node < n_nodes) {
                        #pragma unroll
                        for (int t = 0; t < 4; t++) {
                            int Lb = 64 * wn + 16 * t + q4;
                            uint2 o;
                            o.x = packh2(acc[mt][2*t  ][2*h+0], acc[mt][2*t  ][2*h+1]);
                            o.y = packh2(acc[mt][2*t+1][2*h+0], acc[mt][2*t+1][2*h+1]);
                            *(uint2*)(g_V + node * 64 + (Lb >> 1)) = o;
                        }
                    }
                }
            }
        }
        __syncthreads();
    }
}

// ================= main persistent kernel: 2 independent 4-warp pipelines =====
__global__ void __launch_bounds__(THREADS, 2)
edge_conv_mma(const float* __restrict__ eattr,
              const int*   __restrict__ eidx,
              const float* __restrict__ be,
              float* __restrict__ out,
              int E, int n_nodes)
{
    extern __shared__ char smc[];
    const uint32_t sb = smem_u32(smc);

    const int tid  = threadIdx.x;
    const int wid  = tid >> 5;
    const int lane = tid & 31;
    const int wg   = wid >> 2;          // group 0/1 (independent pipeline)
    const int gtid = tid & 127;         // thread within group
    const int wl   = wid & 3;           // warp within group
    const int wm   = wl & 1;            // row group (32 of 64 edges)
    const int wn   = wl >> 1;           // col group (64 cols)
    const int rq   = lane >> 2;
    const int q4   = (lane & 3) * 4;
    const int bid  = 1 + wg;            // named barrier id
    const uint32_t aOff = OFF_A + (uint32_t)wg * 16384;
    const int ntiles = (E + ET - 1) / ET;

    // ---- common prologue: resident W2 + W3 images ----
    #pragma unroll
    for (int it = 0; it < 16; it++) {
        int i = tid + it * THREADS;              // < 4096
        cp16(sb + OFF_WA + i * 16, (const uint4*)g_wimg + 2 * 2048 + i);
    }
    cp_commit();
    cp_wait0();
    __syncthreads();   // weights resident; groups now fully independent

    for (int tile = blockIdx.x * 2 + wg; tile < ntiles; tile += gridDim.x * 2) {
        const long long e0 = (long long)tile * ET;

        // --- stage eattr (fp32 -> fp16) into this group's A (1024 chunks) ---
        #pragma unroll 4
        for (int it = 0; it < 8; it++) {
            int i = gtid + it * 128;
            int e = i >> 4, c = i & 15;
            long long ge = e0 + e; if (ge >= E) ge = E - 1;
            const float4* s = (const float4*)(eattr + ge * NH + c * 8);
            float4 fa = __ldg(s), fb = __ldg(s + 1);
            uint4 h;
            h.x = packh2(fa.x, fa.y);
            h.y = packh2(fa.z, fa.w);
            h.z = packh2(fb.x, fb.y);
            h.w = packh2(fb.z, fb.w);
            uint32_t off = (uint32_t)(e * 256 + ((c ^ (e & 7)) << 4));
            *(uint4*)(smc + aOff + off) = h;
        }
        barg(bid);         // B1: A staged

        // --- hoist idx loads (latency hides under GEMM1) ---
        int rn4[4], cn4[4];
        #pragma unroll
        for (int mt = 0; mt < 2; mt++) {
            #pragma unroll
            for (int h = 0; h < 2; h++) {
                int row = 32 * wm + 16 * mt + 8 * h + rq;
                long long ge = e0 + row; if (ge >= E) ge = E - 1;
                int rn = __ldg(eidx + ge);
                int cn = __ldg(eidx + (long long)E + ge);
                rn4[mt * 2 + h] = min(max(rn, 0), n_nodes - 1);
                cn4[mt * 2 + h] = min(max(cn, 0), n_nodes - 1);
            }
        }

        float acc[2][8][4];
        #pragma unroll
        for (int i = 0; i < 2; i++)
            #pragma unroll
            for (int j = 0; j < 8; j++)
                #pragma unroll
                for (int q = 0; q < 4; q++) acc[i][j][q] = 0.0f;

        // =========== GEMM 1: ea @ W2 ===========
        do_gemm(sb, aOff, OFF_WA, acc, wm, wn, lane);

        // --- prefetch u/v batch 0 ---
        uint2 puu[4], pvv[4];
        {
            const uint32_t* urow = g_U + rn4[0] * 64;
            const uint32_t* vrow = g_V + cn4[0] * 64;
            #pragma unroll
            for (int t = 0; t < 4; t++) {
                int Lb = 64 * wn + 16 * t + q4;
                puu[t] = *(const uint2*)(urow + (Lb >> 1));
                pvv[t] = *(const uint2*)(vrow + (Lb >> 1));
            }
        }
        barg(bid);         // B2: A readers done before epi1 RMW

        // ==== epilogue 1: ea2 = ea + relu(u[row] + v[col] + ea@W2), RMW A ====
        #pragma unroll
        for (int i = 0; i < 4; i++) {
            const int mt = i >> 1, h = i & 1;
            uint2 cuu[4], cvv[4];
            #pragma unroll
            for (int t = 0; t < 4; t++) { cuu[t] = puu[t]; cvv[t] = pvv[t]; }
            if (i < 3) {
                const uint32_t* urow = g_U + rn4[i + 1] * 64;
                const uint32_t* vrow = g_V + cn4[i + 1] * 64;
                #pragma unroll
                for (int t = 0; t < 4; t++) {
                    int Lb = 64 * wn + 16 * t + q4;
                    puu[t] = *(const uint2*)(urow + (Lb >> 1));
                    pvv[t] = *(const uint2*)(vrow + (Lb >> 1));
                }
            }
            const int row = 32 * wm + 16 * mt + 8 * h + rq;
            #pragma unroll
            for (int t = 0; t < 4; t++) {
                int Lb = 64 * wn + 16 * t + q4;
                uint32_t addr = (uint32_t)(row * 256 +
                                (((Lb >> 3) ^ (row & 7)) << 4) + ((Lb & 7) << 1));
                uint2 ea = *(uint2*)(smc + aOff + addr);
                float2 u0 = unpackh2(cuu[t].x), u1 = unpackh2(cuu[t].y);
                float2 v0 = unpackh2(cvv[t].x), v1 = unpackh2(cvv[t].y);
                float2 ev0 = unpackh2(ea.x), ev1 = unpackh2(ea.y);
                float r0 = ev0.x + frelu(acc[mt][2*t  ][2*h+0] + u0.x + v0.x);
                float r1 = ev0.y + frelu(acc[mt][2*t  ][2*h+1] + u0.y + v0.y);
                float r2 = ev1.x + frelu(acc[mt][2*t+1][2*h+0] + u1.x + v1.x);
                float r3 = ev1.y + frelu(acc[mt][2*t+1][2*h+1] + u1.y + v1.y);
                uint2 o; o.x = packh2(r0, r1); o.y = packh2(r2, r3);
                *(uint2*)(smc + aOff + addr) = o;
                acc[mt][2*t  ][2*h+0] = 0.0f; acc[mt][2*t  ][2*h+1] = 0.0f;
                acc[mt][2*t+1][2*h+0] = 0.0f; acc[mt][2*t+1][2*h+1] = 0.0f;
            }
        }
        barg(bid);         // B3: ea2 complete across the group

        // =========== GEMM 2: ea2 @ W_edge ===========
        do_gemm(sb, aOff, OFF_WB, acc, wm, wn, lane);

        // ===== epilogue 2 (acc -> gmem only; no smem hazard) =====
        {
            #pragma unroll
            for (int mt = 0; mt < 2; mt++) {
                #pragma unroll
                for (int h = 0; h < 2; h++) {
                    int row = 32 * wm + 16 * mt + 8 * h + rq;
                    long long ge = e0 + row;
                    if (ge < E) {
                        #pragma unroll
                        for (int t = 0; t < 4; t++) {
                            int Lb = 64 * wn + 16 * t + q4;
                            float4 bev = __ldg((const float4*)(be + Lb));
                            float4 o;
                            o.x = frelu(acc[mt][2*t  ][2*h+0] + bev.x);
                            o.y = frelu(acc[mt][2*t  ][2*h+1] + bev.y);
                            o.z = frelu(acc[mt][2*t+1][2*h+0] + bev.z);
                            o.w = frelu(acc[mt][2*t+1][2*h+1] + bev.w);
                            *(float4*)(out + ge * NH + Lb) = o;
                        }
                    }
                }
            }
        }
        barg(bid);         // B4: A consumed -> next tile may restage
    }
}

// ================= host =================
extern "C" void kernel_launch(void* const* d_in, const int* in_sizes, int n_in,
                              void* d_out, int out_size)
{
    const float* x     = (const float*)d_in[0];
    const float* eattr = (const float*)d_in[1];
    const int*   eidx  = (const int*)d_in[2];   // int32 (JAX canonicalizes int64->int32)
    const float* Wm    = (const float*)d_in[3];
    const float* bm    = (const float*)d_in[4];
    const float* We    = (const float*)d_in[5];
    const float* be    = (const float*)d_in[6];
    float*       out   = (float*)d_out;

    const int E  = in_sizes[2] / 2;
    int n_nodes  = in_sizes[0] / NH;
    if (n_nodes > MAX_NODES) n_nodes = MAX_NODES;

    prep_w_kernel<<<(65536 + 255) / 256, 256>>>(Wm, We);

    cudaFuncSetAttribute(prep_uv_kernel,
                         cudaFuncAttributeMaxDynamicSharedMemorySize, SMEM_TOTAL);
    cudaFuncSetAttribute(edge_conv_mma,
                         cudaFuncAttributeMaxDynamicSharedMemorySize, SMEM_TOTAL);

    int nsm = 148;
    cudaDeviceGetAttribute(&nsm, cudaDevAttrMultiProcessorCount, 0);

    const int ntileN = (n_nodes + 127) / 128;
    int gridN = 2 * nsm < ntileN ? 2 * nsm : ntileN;
    prep_uv_kernel<<<gridN, THREADS, SMEM_TOTAL>>>(x, bm, n_nodes);

    const int ntiles = (E + ET - 1) / ET;
    int grid = 2 * nsm;
    int maxg = (ntiles + 1) / 2;
    if (grid > maxg) grid = maxg;
    edge_conv_mma<<<grid, THREADS, SMEM_TOTAL>>>(eattr, eidx, be, out, E, n_nodes);
}